// round 2
// baseline (speedup 1.0000x reference)
#include <cuda_runtime.h>
#include <cstddef>

// Problem constants
#define NX 64
#define NU 32
#define NY 32
#define NW 64
#define BB 256
#define TT 2048

// Fused weight scratch (device globals — allocation-free scratch per harness rules)
// gWz: [64][96]  = [ C2*t_inv | D21*t_inv ]        (z rows)
// gWx: [64][160] = [ Yinv^T A | Yinv^T B1 | Yinv^T B2 ]  (x_next rows)
// gWy: [32][160] = [ C1 | D11 | D12 ]               (y rows)
__device__ float gWz[64 * 96];
__device__ float gWx[64 * 160];
__device__ float gWy[32 * 160];

// ---------------------------------------------------------------------------
// Setup: invert Y (Gauss-Jordan, no pivoting — Y = I + 0.01*N, diag dominant),
// fold Y_inv and t_inv into the weights.
// ---------------------------------------------------------------------------
__global__ void setup_kernel(const float* __restrict__ Y,
                             const float* __restrict__ lambdas,
                             const float* __restrict__ A,
                             const float* __restrict__ B1,
                             const float* __restrict__ B2,
                             const float* __restrict__ C1,
                             const float* __restrict__ D11,
                             const float* __restrict__ D12,
                             const float* __restrict__ C2,
                             const float* __restrict__ D21)
{
    __shared__ float M[64][128];   // augmented [Y | I]
    const int tid = threadIdx.x;   // 256 threads

    for (int e = tid; e < 64 * 128; e += 256) {
        int i = e >> 7, j = e & 127;
        M[i][j] = (j < 64) ? Y[i * 64 + j] : ((j - 64 == i) ? 1.0f : 0.0f);
    }
    __syncthreads();

    for (int k = 0; k < 64; k++) {
        float pinv = 1.0f / M[k][k];   // read before any write this iter
        __syncthreads();
        for (int j = tid; j < 128; j += 256) M[k][j] *= pinv;
        __syncthreads();
        // elimination: pre-read multipliers, barrier, then update
        float f[32];
        #pragma unroll
        for (int s = 0; s < 32; s++) {
            int e = tid + 256 * s;
            f[s] = M[e >> 7][k];
        }
        __syncthreads();
        #pragma unroll
        for (int s = 0; s < 32; s++) {
            int e = tid + 256 * s;
            int i = e >> 7, c = e & 127;
            if (i != k) M[i][c] -= f[s] * M[k][c];
        }
        __syncthreads();
    }
    // Yinv[i][j] = M[i][64+j]

    // gWx: Atil[j][k] = sum_i Yinv[i][j]*A[i][k]   (and B2til analog)
    for (int e = tid; e < 64 * 64; e += 256) {
        int j = e >> 6, k2 = e & 63;
        float sA = 0.0f, sB2 = 0.0f;
        #pragma unroll 8
        for (int i = 0; i < 64; i++) {
            float yi = M[i][64 + j];
            sA  += yi * A[i * 64 + k2];
            sB2 += yi * B2[i * 64 + k2];
        }
        gWx[j * 160 + k2]      = sA;
        gWx[j * 160 + 96 + k2] = sB2;
    }
    for (int e = tid; e < 64 * 32; e += 256) {
        int j = e >> 5, m = e & 31;
        float s = 0.0f;
        #pragma unroll 8
        for (int i = 0; i < 64; i++) s += M[i][64 + j] * B1[i * 32 + m];
        gWx[j * 160 + 64 + m] = s;
    }
    // gWz: t_inv row scaling
    for (int e = tid; e < 64 * 64; e += 256) {
        int j = e >> 6, k2 = e & 63;
        gWz[j * 96 + k2] = C2[j * 64 + k2] / lambdas[j];
    }
    for (int e = tid; e < 64 * 32; e += 256) {
        int j = e >> 5, m = e & 31;
        gWz[j * 96 + 64 + m] = D21[j * 32 + m] / lambdas[j];
    }
    // gWy: plain copy into fused layout
    for (int e = tid; e < 32 * 64; e += 256) {
        int j = e >> 6, k2 = e & 63;
        gWy[j * 160 + k2]      = C1[j * 64 + k2];
        gWy[j * 160 + 96 + k2] = D12[j * 64 + k2];
    }
    for (int e = tid; e < 32 * 32; e += 256) {
        int j = e >> 5, m = e & 31;
        gWy[j * 160 + 64 + m] = D11[j * 32 + m];
    }
}

// ---------------------------------------------------------------------------
// Main recurrent kernel: 128 CTAs x 320 threads, 2 batch chains per CTA.
// Thread = (batch, output-row). Operand vector v = [x(64) | u(32) | w(64)].
//   Phase 1: row . v[0:96]  (x,u terms); z-rows apply tanh, publish w.
//   Phase 2: rows 64..159 add row . v[96:160] (w terms); publish x_next / y;
//            z-rows (first 32) prefetch u_{t+1}.
// ---------------------------------------------------------------------------

// smem layout (floats): Wz 64x100 | Wx 64x164 | Wy 32x164 | v 2x160
#define SWZ_OFF 0
#define SWX_OFF (64 * 100)
#define SWY_OFF (SWX_OFF + 64 * 164)
#define SV_OFF  (SWY_OFF + 32 * 164)
#define SMEM_FLOATS (SV_OFF + 2 * 160)

__global__ void __launch_bounds__(320, 1)
rnn_kernel(const float* __restrict__ xpred, float* __restrict__ out, int write_xfinal)
{
    extern __shared__ float sm[];
    float* sWz = sm + SWZ_OFF;
    float* sWx = sm + SWX_OFF;
    float* sWy = sm + SWY_OFF;
    float* sv  = sm + SV_OFF;

    const int tid = threadIdx.x;

    // Stage fused weights into padded smem rows
    for (int e = tid; e < 64 * 96;  e += 320) sWz[(e / 96)  * 100 + (e % 96)]  = gWz[e];
    for (int e = tid; e < 64 * 160; e += 320) sWx[(e / 160) * 164 + (e % 160)] = gWx[e];
    for (int e = tid; e < 32 * 160; e += 320) sWy[(e / 160) * 164 + (e % 160)] = gWy[e];

    const int b = tid / 160;       // local batch 0/1
    const int r = tid % 160;       // output row: [0,64) z, [64,128) x_next, [128,160) y
    float* v = sv + b * 160;
    const int bg = blockIdx.x * 2 + b;
    const float* uptr = xpred + (size_t)bg * TT * NU;
    float* yout = out + (size_t)bg * TT * NY;

    const float* Wrow;
    if (r < 64)       Wrow = sWz + r * 100;
    else if (r < 128) Wrow = sWx + (r - 64) * 164;
    else              Wrow = sWy + (r - 128) * 164;

    // init: x0 = 0; preload u_0
    if (r < 64)            v[r] = 0.0f;
    if (r >= 64 && r < 96) v[r] = uptr[r - 64];
    __syncthreads();

    for (int t = 0; t < TT; t++) {
        // --- Phase 1: x/u terms (chunks 0..23 over v[0:96]) ---
        float a0 = 0.f, a1 = 0.f, a2 = 0.f, a3 = 0.f;
        #pragma unroll
        for (int c = 0; c < 24; c++) {
            float4 w  = *(const float4*)(Wrow + 4 * c);
            float4 xv = *(const float4*)(v + 4 * c);
            a0 += w.x * xv.x;
            a1 += w.y * xv.y;
            a2 += w.z * xv.z;
            a3 += w.w * xv.w;
        }
        float acc = (a0 + a1) + (a2 + a3);
        if (r < 64) v[96 + r] = tanhf(acc);   // publish w
        __syncthreads();

        // --- Phase 2: w terms (chunks 24..39 over v[96:160]) ---
        if (r >= 64) {
            float b0 = 0.f, b1 = 0.f, b2 = 0.f, b3 = 0.f;
            #pragma unroll
            for (int c = 24; c < 40; c++) {
                float4 w  = *(const float4*)(Wrow + 4 * c);
                float4 wv = *(const float4*)(v + 4 * c);
                b0 += w.x * wv.x;
                b1 += w.y * wv.y;
                b2 += w.z * wv.z;
                b3 += w.w * wv.w;
            }
            acc += (b0 + b1) + (b2 + b3);
            if (r < 128) v[r - 64] = acc;               // publish x_next
            else         yout[t * NY + (r - 128)] = acc; // stream y
        } else if (r < 32 && t + 1 < TT) {
            v[64 + r] = uptr[(t + 1) * NU + r];          // prefetch u_{t+1}
        }
        __syncthreads();
    }

    if (write_xfinal && r >= 64 && r < 128) {
        out[(size_t)BB * TT * NY + (size_t)bg * NX + (r - 64)] = v[r - 64];
    }
}

// ---------------------------------------------------------------------------
extern "C" void kernel_launch(void* const* d_in, const int* in_sizes, int n_in,
                              void* d_out, int out_size)
{
    const float* xpred   = (const float*)d_in[0];
    const float* Y       = (const float*)d_in[1];
    const float* lambdas = (const float*)d_in[2];
    const float* A       = (const float*)d_in[3];
    const float* B1      = (const float*)d_in[4];
    const float* B2      = (const float*)d_in[5];
    const float* C1      = (const float*)d_in[6];
    const float* D11     = (const float*)d_in[7];
    const float* D12     = (const float*)d_in[8];
    const float* C2      = (const float*)d_in[9];
    const float* D21     = (const float*)d_in[10];

    (void)in_sizes; (void)n_in;

    size_t smem_bytes = SMEM_FLOATS * sizeof(float);
    cudaFuncSetAttribute(rnn_kernel, cudaFuncAttributeMaxDynamicSharedMemorySize,
                         (int)smem_bytes);

    setup_kernel<<<1, 256>>>(Y, lambdas, A, B1, B2, C1, D11, D12, C2, D21);

    int write_xfinal = (out_size >= BB * TT * NY + BB * NX) ? 1 : 0;
    rnn_kernel<<<BB / 2, 320, smem_bytes>>>(xpred, (float*)d_out, write_xfinal);
}

// round 3
// speedup vs baseline: 1.0964x; 1.0964x over previous
#include <cuda_runtime.h>
#include <cstddef>

// Problem constants
#define NX 64
#define NU 32
#define NY 32
#define NW 64
#define BB 256
#define TT 2048

// Unified fused weight table: gW[160][160], row-major.
//  rows   0..63  (z):  [ C2*t_inv | D21*t_inv | 0        ]
//  rows  64..127 (x):  [ Yinv^T A | Yinv^T B1 | Yinv^T B2]
//  rows 128..159 (y):  [ C1       | D11       | D12      ]
__device__ float gW[160 * 160];

// ---------------------------------------------------------------------------
// Setup: invert Y (Gauss-Jordan, no pivoting — Y = I + 0.01*N, diag dominant),
// fold Y_inv and t_inv into the unified weight table.
// ---------------------------------------------------------------------------
__global__ void setup_kernel(const float* __restrict__ Y,
                             const float* __restrict__ lambdas,
                             const float* __restrict__ A,
                             const float* __restrict__ B1,
                             const float* __restrict__ B2,
                             const float* __restrict__ C1,
                             const float* __restrict__ D11,
                             const float* __restrict__ D12,
                             const float* __restrict__ C2,
                             const float* __restrict__ D21)
{
    __shared__ float M[64][128];   // augmented [Y | I]
    const int tid = threadIdx.x;   // 256 threads

    for (int e = tid; e < 64 * 128; e += 256) {
        int i = e >> 7, j = e & 127;
        M[i][j] = (j < 64) ? Y[i * 64 + j] : ((j - 64 == i) ? 1.0f : 0.0f);
    }
    __syncthreads();

    for (int k = 0; k < 64; k++) {
        float pinv = 1.0f / M[k][k];   // read before any write this iter
        __syncthreads();
        for (int j = tid; j < 128; j += 256) M[k][j] *= pinv;
        __syncthreads();
        float f[32];
        #pragma unroll
        for (int s = 0; s < 32; s++) {
            int e = tid + 256 * s;
            f[s] = M[e >> 7][k];
        }
        __syncthreads();
        #pragma unroll
        for (int s = 0; s < 32; s++) {
            int e = tid + 256 * s;
            int i = e >> 7, c = e & 127;
            if (i != k) M[i][c] -= f[s] * M[k][c];
        }
        __syncthreads();
    }
    // Yinv[i][j] = M[i][64+j]

    // z rows (0..63): t_inv scaling, zero w-part
    for (int e = tid; e < 64 * 64; e += 256) {
        int j = e >> 6, k2 = e & 63;
        gW[j * 160 + k2] = C2[j * 64 + k2] / lambdas[j];
        gW[j * 160 + 96 + k2] = 0.0f;
    }
    for (int e = tid; e < 64 * 32; e += 256) {
        int j = e >> 5, m = e & 31;
        gW[j * 160 + 64 + m] = D21[j * 32 + m] / lambdas[j];
    }
    // x rows (64..127): Atil[j][k] = sum_i Yinv[i][j]*A[i][k] (+B1til, B2til)
    for (int e = tid; e < 64 * 64; e += 256) {
        int j = e >> 6, k2 = e & 63;
        float sA = 0.0f, sB2 = 0.0f;
        #pragma unroll 8
        for (int i = 0; i < 64; i++) {
            float yi = M[i][64 + j];
            sA  += yi * A[i * 64 + k2];
            sB2 += yi * B2[i * 64 + k2];
        }
        gW[(64 + j) * 160 + k2]      = sA;
        gW[(64 + j) * 160 + 96 + k2] = sB2;
    }
    for (int e = tid; e < 64 * 32; e += 256) {
        int j = e >> 5, m = e & 31;
        float s = 0.0f;
        #pragma unroll 8
        for (int i = 0; i < 64; i++) s += M[i][64 + j] * B1[i * 32 + m];
        gW[(64 + j) * 160 + 64 + m] = s;
    }
    // y rows (128..159)
    for (int e = tid; e < 32 * 64; e += 256) {
        int j = e >> 6, k2 = e & 63;
        gW[(128 + j) * 160 + k2]      = C1[j * 64 + k2];
        gW[(128 + j) * 160 + 96 + k2] = D12[j * 64 + k2];
    }
    for (int e = tid; e < 32 * 32; e += 256) {
        int j = e >> 5, m = e & 31;
        gW[(128 + j) * 160 + 64 + m] = D11[j * 32 + m];
    }
}

// ---------------------------------------------------------------------------
// Main recurrent kernel: 128 CTAs x 320 threads, 2 batch chains per CTA.
// Weights live in REGISTERS (80 x u64 per thread); only the shared operand
// vector v = [x(64) | u(32) | w(64)] is in smem (warp-uniform broadcast reads).
// Dot products use packed fma.rn.f32x2 (Blackwell FFMA2, 2 MACs/instr).
// ---------------------------------------------------------------------------

__device__ __forceinline__ float2 u64_as_f2(unsigned long long x) {
    float2 r;
    asm("mov.b64 {%0, %1}, %2;" : "=f"(r.x), "=f"(r.y) : "l"(x));
    return r;
}

#define FFMA2(acc, w, vv) \
    asm("fma.rn.f32x2 %0, %1, %2, %0;" : "+l"(acc) : "l"(w), "l"(vv))

__global__ void __launch_bounds__(320, 1)
rnn_kernel(const float* __restrict__ xpred, float* __restrict__ out, int write_xfinal)
{
    __shared__ __align__(16) float sv[2 * 160];

    const int tid = threadIdx.x;
    const int b = tid / 160;       // local batch 0/1 (warp-aligned: 160 = 5 warps)
    const int r = tid % 160;       // output row: [0,64) z, [64,128) x_next, [128,160) y
    float* v = sv + b * 160;
    const int bg = blockIdx.x * 2 + b;
    const float* uptr = xpred + (size_t)bg * TT * NU;
    float* yout = out + (size_t)bg * TT * NY;

    // Load this thread's weight row into registers (one-time).
    unsigned long long wreg[80];
    {
        const unsigned long long* grow =
            (const unsigned long long*)(gW + r * 160);
        #pragma unroll
        for (int i = 0; i < 80; i++) wreg[i] = grow[i];
    }

    // init: x0 = 0; u_0 into v; u_1 into the prefetch register
    if (r < 64) v[r] = 0.0f;
    float u_next = 0.0f;
    if (r < 32) {
        v[64 + r] = uptr[r];
        u_next = uptr[NU + r];
    }
    __syncthreads();

    for (int t = 0; t < TT; t++) {
        // --- Phase 1: x/u terms (v[0:96] = chunks 0..23) ---
        unsigned long long a0 = 0ull, a1 = 0ull;
        #pragma unroll
        for (int c = 0; c < 24; c++) {
            ulonglong2 vv = *(const ulonglong2*)(v + 4 * c);
            FFMA2(a0, wreg[2 * c],     vv.x);
            FFMA2(a1, wreg[2 * c + 1], vv.y);
        }
        float2 p = u64_as_f2(a0), q = u64_as_f2(a1);
        float acc = (p.x + q.x) + (p.y + q.y);
        if (r < 64) v[96 + r] = tanhf(acc);   // publish w
        __syncthreads();

        // --- Phase 2: w terms (v[96:160] = chunks 24..39) ---
        if (r >= 64) {
            unsigned long long b0 = 0ull, b1 = 0ull;
            #pragma unroll
            for (int c = 24; c < 40; c++) {
                ulonglong2 vv = *(const ulonglong2*)(v + 4 * c);
                FFMA2(b0, wreg[2 * c],     vv.x);
                FFMA2(b1, wreg[2 * c + 1], vv.y);
            }
            float2 s = u64_as_f2(b0), w2 = u64_as_f2(b1);
            acc += (s.x + w2.x) + (s.y + w2.y);
            if (r < 128) v[r - 64] = acc;                 // publish x_next
            else         yout[t * NY + (r - 128)] = acc;  // stream y
        } else if (r < 32) {
            v[64 + r] = u_next;                            // u_{t+1} (loaded 2 steps ago)
            if (t + 2 < TT) u_next = uptr[(t + 2) * NU + r];
        }
        __syncthreads();
    }

    if (write_xfinal && r >= 64 && r < 128) {
        out[(size_t)BB * TT * NY + (size_t)bg * NX + (r - 64)] = v[r - 64];
    }
}

// ---------------------------------------------------------------------------
extern "C" void kernel_launch(void* const* d_in, const int* in_sizes, int n_in,
                              void* d_out, int out_size)
{
    const float* xpred   = (const float*)d_in[0];
    const float* Y       = (const float*)d_in[1];
    const float* lambdas = (const float*)d_in[2];
    const float* A       = (const float*)d_in[3];
    const float* B1      = (const float*)d_in[4];
    const float* B2      = (const float*)d_in[5];
    const float* C1      = (const float*)d_in[6];
    const float* D11     = (const float*)d_in[7];
    const float* D12     = (const float*)d_in[8];
    const float* C2      = (const float*)d_in[9];
    const float* D21     = (const float*)d_in[10];

    (void)in_sizes; (void)n_in;

    setup_kernel<<<1, 256>>>(Y, lambdas, A, B1, B2, C1, D11, D12, C2, D21);

    int write_xfinal = (out_size >= BB * TT * NY + BB * NX) ? 1 : 0;
    rnn_kernel<<<BB / 2, 320>>>(xpred, (float*)d_out, write_xfinal);
}

// round 4
// speedup vs baseline: 1.7563x; 1.6019x over previous
#include <cuda_runtime.h>
#include <cstddef>

// Problem constants
#define NX 64
#define NU 32
#define NY 32
#define NW 64
#define BB 256
#define TT 2048

// Fused weight table gW[160][160] (row-major), built by setup_kernel:
//  rows   0..63  (z):  [ C2*t_inv | D21*t_inv | 0        ]
//  rows  64..127 (x):  [ Yinv^T A | Yinv^T B1 | Yinv^T B2]
//  rows 128..159 (y):  [ C1       | D11       | D12      ]
__device__ float gW[160 * 160];

// Per-thread packed weights: gWT[s][96], s = tid%256.
//  s in [0,64)   : z row s, 96 floats (k 0..95)
//  s in [64,192) : x row 64+(s-64)/2, half h=(s-64)&1: 20 chunks c=h,h+2,..,h+38 (80 floats)
//  s in [192,256): y row 128+(s-192)/2, same half scheme
__device__ float gWT[256 * 96];

// ---------------------------------------------------------------------------
// Setup: invert Y (Gauss-Jordan, diag dominant), fold Y_inv and t_inv.
// ---------------------------------------------------------------------------
__global__ void setup_kernel(const float* __restrict__ Y,
                             const float* __restrict__ lambdas,
                             const float* __restrict__ A,
                             const float* __restrict__ B1,
                             const float* __restrict__ B2,
                             const float* __restrict__ C1,
                             const float* __restrict__ D11,
                             const float* __restrict__ D12,
                             const float* __restrict__ C2,
                             const float* __restrict__ D21)
{
    __shared__ float M[64][128];   // augmented [Y | I]
    const int tid = threadIdx.x;   // 256 threads

    for (int e = tid; e < 64 * 128; e += 256) {
        int i = e >> 7, j = e & 127;
        M[i][j] = (j < 64) ? Y[i * 64 + j] : ((j - 64 == i) ? 1.0f : 0.0f);
    }
    __syncthreads();

    for (int k = 0; k < 64; k++) {
        float pinv = 1.0f / M[k][k];
        __syncthreads();
        for (int j = tid; j < 128; j += 256) M[k][j] *= pinv;
        __syncthreads();
        float f[32];
        #pragma unroll
        for (int s = 0; s < 32; s++) {
            int e = tid + 256 * s;
            f[s] = M[e >> 7][k];
        }
        __syncthreads();
        #pragma unroll
        for (int s = 0; s < 32; s++) {
            int e = tid + 256 * s;
            int i = e >> 7, c = e & 127;
            if (i != k) M[i][c] -= f[s] * M[k][c];
        }
        __syncthreads();
    }
    // Yinv[i][j] = M[i][64+j]

    // z rows
    for (int e = tid; e < 64 * 64; e += 256) {
        int j = e >> 6, k2 = e & 63;
        gW[j * 160 + k2] = C2[j * 64 + k2] / lambdas[j];
        gW[j * 160 + 96 + k2] = 0.0f;
    }
    for (int e = tid; e < 64 * 32; e += 256) {
        int j = e >> 5, m = e & 31;
        gW[j * 160 + 64 + m] = D21[j * 32 + m] / lambdas[j];
    }
    // x rows
    for (int e = tid; e < 64 * 64; e += 256) {
        int j = e >> 6, k2 = e & 63;
        float sA = 0.0f, sB2 = 0.0f;
        #pragma unroll 8
        for (int i = 0; i < 64; i++) {
            float yi = M[i][64 + j];
            sA  += yi * A[i * 64 + k2];
            sB2 += yi * B2[i * 64 + k2];
        }
        gW[(64 + j) * 160 + k2]      = sA;
        gW[(64 + j) * 160 + 96 + k2] = sB2;
    }
    for (int e = tid; e < 64 * 32; e += 256) {
        int j = e >> 5, m = e & 31;
        float s = 0.0f;
        #pragma unroll 8
        for (int i = 0; i < 64; i++) s += M[i][64 + j] * B1[i * 32 + m];
        gW[(64 + j) * 160 + 64 + m] = s;
    }
    // y rows
    for (int e = tid; e < 32 * 64; e += 256) {
        int j = e >> 6, k2 = e & 63;
        gW[(128 + j) * 160 + k2]      = C1[j * 64 + k2];
        gW[(128 + j) * 160 + 96 + k2] = D12[j * 64 + k2];
    }
    for (int e = tid; e < 32 * 32; e += 256) {
        int j = e >> 5, m = e & 31;
        gW[(128 + j) * 160 + 64 + m] = D11[j * 32 + m];
    }
}

// Pack gW into per-thread layout gWT.
__global__ void pack_kernel()
{
    const int s = threadIdx.x;   // 256 threads
    if (s < 64) {
        // z row: contiguous k 0..95
        for (int j = 0; j < 96; j++) gWT[s * 96 + j] = gW[s * 160 + j];
    } else {
        int r, h;
        if (s < 192) { r = 64 + ((s - 64) >> 1);  h = (s - 64) & 1; }
        else         { r = 128 + ((s - 192) >> 1); h = (s - 192) & 1; }
        for (int i = 0; i < 20; i++) {
            int c = h + 2 * i;
            for (int j = 0; j < 4; j++)
                gWT[s * 96 + 4 * i + j] = gW[r * 160 + 4 * c + j];
        }
        for (int j = 80; j < 96; j++) gWT[s * 96 + j] = 0.0f;
    }
}

// ---------------------------------------------------------------------------
// Main recurrent kernel: 128 CTAs x 512 threads, 2 batch chains per CTA.
// Per batch: 64 z threads (96 reg-weights each) + 96 rows x 2 half-threads
// (80 reg-weights each). v = [x(64)|u(32)|w(64)] in smem, warp-broadcast reads.
// Packed fma.rn.f32x2; per-batch named barriers.
// ---------------------------------------------------------------------------

__device__ __forceinline__ float2 u64_as_f2(unsigned long long x) {
    float2 r;
    asm("mov.b64 {%0, %1}, %2;" : "=f"(r.x), "=f"(r.y) : "l"(x));
    return r;
}

#define FFMA2(acc, w, vv) \
    asm("fma.rn.f32x2 %0, %1, %2, %0;" : "+l"(acc) : "l"(w), "l"(vv))

#define BARB(id) asm volatile("bar.sync %0, 256;" :: "r"(id) : "memory")

__global__ void __launch_bounds__(512, 1)
rnn_kernel(const float* __restrict__ xpred, float* __restrict__ out, int write_xfinal)
{
    __shared__ __align__(16) float sv[2 * 160];

    const int tid   = threadIdx.x;
    const int batch = tid >> 8;        // 0/1
    const int s     = tid & 255;
    float* v = sv + batch * 160;
    const int bg = blockIdx.x * 2 + batch;
    const float* uptr = xpred + (size_t)bg * TT * NU;
    float* yout = out + (size_t)bg * TT * NY;
    const int barid = batch + 1;

    const bool isZ = (s < 64);
    int r, h = 0;
    if (s < 64)       { r = s; }
    else if (s < 192) { r = 64  + ((s - 64)  >> 1); h = (s - 64)  & 1; }
    else              { r = 128 + ((s - 192) >> 1); h = (s - 192) & 1; }

    // One-time weight load into registers (warp-uniform branch).
    unsigned long long wreg[48];
    {
        const unsigned long long* grow = (const unsigned long long*)(gWT + s * 96);
        #pragma unroll
        for (int i = 0; i < 40; i++) wreg[i] = grow[i];
        if (isZ) {
            #pragma unroll
            for (int i = 40; i < 48; i++) wreg[i] = grow[i];
        } else {
            #pragma unroll
            for (int i = 40; i < 48; i++) wreg[i] = 0ull;
        }
    }

    // init: x0 = 0; u_0 into v; u_1 into prefetch reg
    if (s < 64) v[s] = 0.0f;
    float u_next = 0.0f;
    if (s < 32) {
        v[64 + s] = uptr[s];
        u_next = uptr[NU + s];
    }
    BARB(barid);

    const float* vh = v + 4 * h;   // x/y: this half's first chunk

    for (int t = 0; t < TT; t++) {
        unsigned long long a0 = 0ull, a1 = 0ull;

        if (isZ) {
            // --- Phase 1 (z): all 24 chunks of v[0:96], 4 accumulators ---
            unsigned long long a2 = 0ull, a3 = 0ull;
            #pragma unroll
            for (int c = 0; c < 24; c += 2) {
                ulonglong2 v0 = *(const ulonglong2*)(v + 4 * c);
                ulonglong2 v1 = *(const ulonglong2*)(v + 4 * c + 4);
                FFMA2(a0, wreg[2 * c],     v0.x);
                FFMA2(a1, wreg[2 * c + 1], v0.y);
                FFMA2(a2, wreg[2 * c + 2], v1.x);
                FFMA2(a3, wreg[2 * c + 3], v1.y);
            }
            float2 p = u64_as_f2(a0), q = u64_as_f2(a1);
            float2 p2 = u64_as_f2(a2), q2 = u64_as_f2(a3);
            float acc = ((p.x + q.x) + (p.y + q.y)) + ((p2.x + q2.x) + (p2.y + q2.y));
            v[96 + r] = tanhf(acc);          // publish w
        } else {
            // --- Phase 1 (x/y): this half's 12 chunks of v[0:96] ---
            #pragma unroll
            for (int i = 0; i < 12; i++) {
                ulonglong2 vv = *(const ulonglong2*)(vh + 8 * i);
                FFMA2(a0, wreg[2 * i],     vv.x);
                FFMA2(a1, wreg[2 * i + 1], vv.y);
            }
        }
        BARB(barid);   // w visible

        if (!isZ) {
            // --- Phase 2 (x/y): this half's 8 chunks of v[96:160] ---
            #pragma unroll
            for (int i = 12; i < 20; i++) {
                ulonglong2 vv = *(const ulonglong2*)(vh + 8 * i);
                FFMA2(a0, wreg[2 * i],     vv.x);
                FFMA2(a1, wreg[2 * i + 1], vv.y);
            }
            float2 p = u64_as_f2(a0), q = u64_as_f2(a1);
            float acc = (p.x + q.x) + (p.y + q.y);
            acc += __shfl_xor_sync(0xffffffffu, acc, 1);   // combine halves
            if (h == 0) {
                if (r < 128) v[r - 64] = acc;                 // publish x_next
                else         yout[t * NY + (r - 128)] = acc;  // stream y
            }
        } else if (s < 32) {
            v[64 + s] = u_next;                               // u_{t+1}
            if (t + 2 < TT) u_next = uptr[(t + 2) * NU + s];
        }
        BARB(barid);   // x_next/u visible
    }

    if (write_xfinal && s < 64) {
        out[(size_t)BB * TT * NY + (size_t)bg * NX + s] = v[s];
    }
}

// ---------------------------------------------------------------------------
extern "C" void kernel_launch(void* const* d_in, const int* in_sizes, int n_in,
                              void* d_out, int out_size)
{
    const float* xpred   = (const float*)d_in[0];
    const float* Y       = (const float*)d_in[1];
    const float* lambdas = (const float*)d_in[2];
    const float* A       = (const float*)d_in[3];
    const float* B1      = (const float*)d_in[4];
    const float* B2      = (const float*)d_in[5];
    const float* C1      = (const float*)d_in[6];
    const float* D11     = (const float*)d_in[7];
    const float* D12     = (const float*)d_in[8];
    const float* C2      = (const float*)d_in[9];
    const float* D21     = (const float*)d_in[10];

    (void)in_sizes; (void)n_in;

    setup_kernel<<<1, 256>>>(Y, lambdas, A, B1, B2, C1, D11, D12, C2, D21);
    pack_kernel<<<1, 256>>>();

    int write_xfinal = (out_size >= BB * TT * NY + BB * NX) ? 1 : 0;
    rnn_kernel<<<BB / 2, 512>>>(xpred, (float*)d_out, write_xfinal);
}